// round 4
// baseline (speedup 1.0000x reference)
#include <cuda_runtime.h>
#include <math.h>
#include <stdint.h>

#define T_STEPS 20
#define BATCH   64
#define PIX     196
#define ENC_C   256
#define ATT_D   512
#define DEC_D   512
#define EMB_D   512
#define VOCAB   30000
#define GATES   2048

// ---------------- device scratch (static; no allocations allowed) ----------
__device__ float g_feats[BATCH * PIX * ENC_C];      // [b][p][c]
__device__ float g_enc_att[BATCH * PIX * ATT_D];    // [b][p][a]
__device__ float g_E[T_STEPS * BATCH * EMB_D];      // row m = t*64+b
__device__ float g_xg[T_STEPS * BATCH * GATES];     // emb part of gates (+biases)
__device__ float g_dec[BATCH * ATT_D];              // h @ W_dec + b_dec
__device__ float g_gates[BATCH * GATES];
__device__ float g_h[2][BATCH * DEC_D];             // double-buffered hidden
__device__ float g_c[BATCH * DEC_D];
__device__ float g_ctx[BATCH * ENC_C];
__device__ float g_Hall[T_STEPS * BATCH * DEC_D];   // all h_t, row m = t*64+b
__device__ float g_bias2[GATES];                    // b_ih + b_hh
__device__ int   g_cap64;

// ---------------- f32x2 helpers --------------------------------------------
__device__ __forceinline__ unsigned long long pk2(float lo, float hi) {
    unsigned long long r;
    asm("mov.b64 %0, {%1, %2};" : "=l"(r) : "f"(lo), "f"(hi));
    return r;
}
__device__ __forceinline__ void fma2(unsigned long long &d, unsigned long long a,
                                     unsigned long long b) {
    asm("fma.rn.f32x2 %0, %1, %2, %0;" : "+l"(d) : "l"(a), "l"(b));
}
__device__ __forceinline__ float2 upk(unsigned long long v) {
    float2 r;
    asm("mov.b64 {%0, %1}, %2;" : "=f"(r.x), "=f"(r.y) : "l"(v));
    return r;
}
__device__ __forceinline__ float sigmoidf_(float x) { return 1.f / (1.f + expf(-x)); }

// ---------------- init ------------------------------------------------------
__global__ void k_init(const float* __restrict__ b_ih, const float* __restrict__ b_hh,
                       const void* __restrict__ caps) {
    int idx = blockIdx.x * 256 + threadIdx.x;
    if (idx < BATCH * DEC_D) g_h[0][idx] = 0.f;
    else if (idx < 2 * BATCH * DEC_D) g_c[idx - BATCH * DEC_D] = 0.f;
    else if (idx < 2 * BATCH * DEC_D + GATES) {
        int n = idx - 2 * BATCH * DEC_D;
        g_bias2[n] = b_ih[n] + b_hh[n];
    }
    if (blockIdx.x == 0 && threadIdx.x == 0) {
        const int* ci = (const int*)caps;
        int all0 = 1;
        for (int i = 0; i < 64; i++) if (ci[2 * i + 1] != 0) { all0 = 0; break; }
        g_cap64 = all0;
    }
}

// ---------------- transpose [b][c][p] -> feats [b][p][c] -------------------
__global__ void k_transpose(const float* __restrict__ in) {
    __shared__ float tile[32][33];
    int b  = blockIdx.z;
    int p0 = blockIdx.x * 32;
    int c0 = blockIdx.y * 32;
    int tx = threadIdx.x, ty = threadIdx.y;
    const float* src = in + ((size_t)b * ENC_C + c0) * PIX + p0;
#pragma unroll
    for (int i = 0; i < 4; i++) {
        int c = ty + i * 8;
        if (p0 + tx < PIX) tile[c][tx] = src[c * PIX + tx];
    }
    __syncthreads();
    float* dst = g_feats + (size_t)b * PIX * ENC_C;
#pragma unroll
    for (int i = 0; i < 4; i++) {
        int p = ty + i * 8;
        if (p0 + p < PIX) dst[(size_t)(p0 + p) * ENC_C + c0 + tx] = tile[tx][p];
    }
}

// ---------------- embedding gather -----------------------------------------
__global__ void k_gather(const void* __restrict__ caps, const float* __restrict__ emb) {
    int m = blockIdx.x;
    int tt = m >> 6, b = m & 63;
    long long cap;
    if (g_cap64) cap = ((const long long*)caps)[b * T_STEPS + tt];
    else         cap = ((const int*)caps)[b * T_STEPS + tt];
    if ((unsigned long long)cap >= (unsigned long long)VOCAB) cap = 0;
    const float4* src = (const float4*)(emb + (size_t)cap * EMB_D);
    float4* dst = (float4*)(g_E + (size_t)m * EMB_D);
    dst[threadIdx.x] = src[threadIdx.x];
}

// ---------------- double-buffered f32x2 GEMM: C = A @ op(B) + bias ---------
// 128(M) x 128(N) block tile, KT=16, 256 threads, 8x8 per thread.
// One __syncthreads per K-chunk; next chunk prefetched into registers.
template <bool TRANSB, bool REMAP>
__global__ __launch_bounds__(256, 2)
void k_gemm2(const float* __restrict__ A, int lda,
             const float* __restrict__ B, int ldb,
             const float* __restrict__ bias,
             float* __restrict__ C, int ldc,
             int M, int N, int K) {
    __shared__ float As[2][16][132];   // [buf][k][m]
    __shared__ float Bs[2][16][132];   // [buf][k][n]
    const int t  = threadIdx.x;
    const int tx = t & 15, ty = t >> 4;
    const int m0 = blockIdx.y * 128, n0 = blockIdx.x * 128;
    const int nc = K / 16;

    // loader indices
    const int ai = t >> 1, akh = (t & 1) << 3;           // A: row ai, k-half akh
    const int bkk = t >> 4, bnq = (t & 15) << 3;         // B NN: k-row bkk, 8 cols bnq
    const int bn  = t >> 1, bkq = (t & 1) << 3;          // B NT: row bn, 8 k bkq

    unsigned long long acc[4][8];
#pragma unroll
    for (int i = 0; i < 4; i++)
#pragma unroll
        for (int j = 0; j < 8; j++) acc[i][j] = 0ull;

    float ra[8], rb[8];

    auto loadG = [&](int k0) {
        {   // A
            int m = m0 + ai;
            float4 v0 = {0,0,0,0}, v1 = {0,0,0,0};
            if (m < M) {
                const float4* p = (const float4*)(A + (size_t)m * lda + k0 + akh);
                v0 = p[0]; v1 = p[1];
            }
            ra[0]=v0.x; ra[1]=v0.y; ra[2]=v0.z; ra[3]=v0.w;
            ra[4]=v1.x; ra[5]=v1.y; ra[6]=v1.z; ra[7]=v1.w;
        }
        if (!TRANSB) {
            float4 v0 = {0,0,0,0}, v1 = {0,0,0,0};
            const float* base = B + (size_t)(k0 + bkk) * ldb + n0 + bnq;
            if (n0 + bnq + 4 <= N) v0 = *(const float4*)base;
            if (n0 + bnq + 8 <= N) v1 = *(const float4*)(base + 4);
            rb[0]=v0.x; rb[1]=v0.y; rb[2]=v0.z; rb[3]=v0.w;
            rb[4]=v1.x; rb[5]=v1.y; rb[6]=v1.z; rb[7]=v1.w;
        } else {
            float4 v0 = {0,0,0,0}, v1 = {0,0,0,0};
            if (n0 + bn < N) {
                const float4* p = (const float4*)(B + (size_t)(n0 + bn) * ldb + k0 + bkq);
                v0 = p[0]; v1 = p[1];
            }
            rb[0]=v0.x; rb[1]=v0.y; rb[2]=v0.z; rb[3]=v0.w;
            rb[4]=v1.x; rb[5]=v1.y; rb[6]=v1.z; rb[7]=v1.w;
        }
    };
    auto storeS = [&](int buf) {
#pragma unroll
        for (int j = 0; j < 8; j++) As[buf][akh + j][ai] = ra[j];
        if (!TRANSB) {
#pragma unroll
            for (int j = 0; j < 8; j++) Bs[buf][bkk][bnq + j] = rb[j];
        } else {
#pragma unroll
            for (int j = 0; j < 8; j++) Bs[buf][bkq + j][bn] = rb[j];
        }
    };

    loadG(0);
    storeS(0);
    __syncthreads();

    for (int c = 0; c < nc; c++) {
        int buf = c & 1;
        if (c + 1 < nc) loadG((c + 1) * 16);
#pragma unroll
        for (int kk = 0; kk < 16; kk++) {
            unsigned long long a2[4];
            a2[0] = *(const unsigned long long*)&As[buf][kk][ty*8+0];
            a2[1] = *(const unsigned long long*)&As[buf][kk][ty*8+2];
            a2[2] = *(const unsigned long long*)&As[buf][kk][ty*8+4];
            a2[3] = *(const unsigned long long*)&As[buf][kk][ty*8+6];
            float4 b40 = *(const float4*)&Bs[buf][kk][tx*8];
            float4 b41 = *(const float4*)&Bs[buf][kk][tx*8+4];
            float bv[8] = {b40.x,b40.y,b40.z,b40.w,b41.x,b41.y,b41.z,b41.w};
#pragma unroll
            for (int j = 0; j < 8; j++) {
                unsigned long long b2 = pk2(bv[j], bv[j]);
                fma2(acc[0][j], a2[0], b2);
                fma2(acc[1][j], a2[1], b2);
                fma2(acc[2][j], a2[2], b2);
                fma2(acc[3][j], a2[3], b2);
            }
        }
        if (c + 1 < nc) storeS(buf ^ 1);
        __syncthreads();
    }

#pragma unroll
    for (int j = 0; j < 8; j++) {
        int col = n0 + tx * 8 + j;
        if (col >= N) continue;
        float bv = bias ? bias[col] : 0.f;
#pragma unroll
        for (int i = 0; i < 4; i++) {
            float2 v = upk(acc[i][j]);
            int m = m0 + ty * 8 + i * 2;
            if (m < M) {
                int r = REMAP ? ((m & 63) * T_STEPS + (m >> 6)) : m;
                C[(size_t)r * ldc + col] = v.x + bv;
            }
            if (m + 1 < M) {
                int m1 = m + 1;
                int r = REMAP ? ((m1 & 63) * T_STEPS + (m1 >> 6)) : m1;
                C[(size_t)r * ldc + col] = v.y + bv;
            }
        }
    }
}

// ---------------- per-step: dec_att = h @ W_dec + b_dec --------------------
__global__ __launch_bounds__(256) void k_dec(const float* __restrict__ W_dec,
                                             const float* __restrict__ b_dec, int t) {
    __shared__ float hs[64][68];
    __shared__ float ws[64][17];
    int tid = threadIdx.x, n0 = blockIdx.x * 16;
    const float* hb = g_h[t & 1];
    int lb = tid & 63, kq = (tid >> 6) * 16;
    int wk = tid >> 2, wq = (tid & 3) * 4;
    int nl = tid & 15, bq = tid >> 4;
    unsigned long long acc0 = 0ull, acc1 = 0ull;
    for (int c = 0; c < 8; c++) {
        int k0 = c * 64;
#pragma unroll
        for (int j = 0; j < 4; j++) {
            float4 v = *(const float4*)(hb + lb * 512 + k0 + kq + j * 4);
            hs[kq+j*4+0][lb]=v.x; hs[kq+j*4+1][lb]=v.y;
            hs[kq+j*4+2][lb]=v.z; hs[kq+j*4+3][lb]=v.w;
        }
        {
            float4 v = *(const float4*)(W_dec + (size_t)(k0 + wk) * 512 + n0 + wq);
            ws[wk][wq]=v.x; ws[wk][wq+1]=v.y; ws[wk][wq+2]=v.z; ws[wk][wq+3]=v.w;
        }
        __syncthreads();
#pragma unroll 16
        for (int kk = 0; kk < 64; kk++) {
            float w = ws[kk][nl];
            unsigned long long w2 = pk2(w, w);
            fma2(acc0, *(const unsigned long long*)&hs[kk][bq*4],   w2);
            fma2(acc1, *(const unsigned long long*)&hs[kk][bq*4+2], w2);
        }
        __syncthreads();
    }
    int n = n0 + nl; float bv = b_dec[n];
    float2 a = upk(acc0), b2 = upk(acc1);
    g_dec[(bq*4+0)*512+n] = a.x + bv;
    g_dec[(bq*4+1)*512+n] = a.y + bv;
    g_dec[(bq*4+2)*512+n] = b2.x + bv;
    g_dec[(bq*4+3)*512+n] = b2.y + bv;
}

// ---------------- per-step: fused attention scores/softmax/context ---------
__global__ __launch_bounds__(256) void k_att(const float* __restrict__ W_full, int t) {
    __shared__ float dec_s[512], wf_s[512], sc_s[224];
    __shared__ float red[8];
    int b = blockIdx.x, tid = threadIdx.x;
    dec_s[tid] = g_dec[b*512+tid]; dec_s[tid+256] = g_dec[b*512+tid+256];
    wf_s[tid] = W_full[tid]; wf_s[tid+256] = W_full[tid+256];
    __syncthreads();
    int wp = tid >> 5, lane = tid & 31;
    for (int p = wp; p < PIX; p += 8) {
        const float* ea = g_enc_att + ((size_t)b * PIX + p) * ATT_D;
        float s = 0.f;
#pragma unroll 4
        for (int a = lane; a < 512; a += 32)
            s = fmaf(fmaxf(ea[a] + dec_s[a], 0.f), wf_s[a], s);
#pragma unroll
        for (int o = 16; o; o >>= 1) s += __shfl_xor_sync(0xffffffffu, s, o);
        if (!lane) sc_s[p] = s;      // +b_full omitted: softmax shift-invariant
    }
    __syncthreads();
    float v = (tid < PIX) ? sc_s[tid] : -1e30f;
    float mx = v;
#pragma unroll
    for (int o = 16; o; o >>= 1) mx = fmaxf(mx, __shfl_xor_sync(0xffffffffu, mx, o));
    if (!lane) red[wp] = mx;
    __syncthreads();
    if (tid == 0) { float m = red[0]; for (int i = 1; i < 8; i++) m = fmaxf(m, red[i]); red[0] = m; }
    __syncthreads();
    float e = (tid < PIX) ? expf(v - red[0]) : 0.f;
    float ss = e;
#pragma unroll
    for (int o = 16; o; o >>= 1) ss += __shfl_xor_sync(0xffffffffu, ss, o);
    __syncthreads();
    if (!lane) red[wp] = ss;
    __syncthreads();
    if (tid == 0) { float s = 0.f; for (int i = 0; i < 8; i++) s += red[i]; red[0] = s; }
    __syncthreads();
    if (tid < PIX) sc_s[tid] = e / red[0];
    __syncthreads();
    const float* fb = g_feats + (size_t)b * PIX * ENC_C;
    float cx = 0.f;
#pragma unroll 4
    for (int p = 0; p < PIX; p++) cx = fmaf(sc_s[p], fb[p * ENC_C + tid], cx);
    g_ctx[b * ENC_C + tid] = cx;
}

// ---------------- per-step: gates = xg + h@W_hh^T + ctx@W_ih[:,512:]^T -----
__global__ __launch_bounds__(256) void k_gates(const float* __restrict__ W_hh,
                                               const float* __restrict__ W_ih, int t) {
    __shared__ float hs[64][68];
    __shared__ float ws[64][17];
    int tid = threadIdx.x, n0 = blockIdx.x * 16;
    const float* hb = g_h[t & 1];
    int lb = tid & 63, kq = (tid >> 6) * 16;
    int wn = tid >> 4, wq = (tid & 15) * 4;
    int nl = tid & 15, bq = tid >> 4;
    unsigned long long acc0 = 0ull, acc1 = 0ull;
    for (int c = 0; c < 12; c++) {
        int k0 = c * 64;
        if (k0 < 512) {
#pragma unroll
            for (int j = 0; j < 4; j++) {
                float4 v = *(const float4*)(hb + lb * 512 + k0 + kq + j * 4);
                hs[kq+j*4+0][lb]=v.x; hs[kq+j*4+1][lb]=v.y;
                hs[kq+j*4+2][lb]=v.z; hs[kq+j*4+3][lb]=v.w;
            }
            float4 v = *(const float4*)(W_hh + (size_t)(n0 + wn) * 512 + k0 + wq);
            ws[wq][wn]=v.x; ws[wq+1][wn]=v.y; ws[wq+2][wn]=v.z; ws[wq+3][wn]=v.w;
        } else {
            int k1 = k0 - 512;
#pragma unroll
            for (int j = 0; j < 4; j++) {
                float4 v = *(const float4*)(g_ctx + lb * 256 + k1 + kq + j * 4);
                hs[kq+j*4+0][lb]=v.x; hs[kq+j*4+1][lb]=v.y;
                hs[kq+j*4+2][lb]=v.z; hs[kq+j*4+3][lb]=v.w;
            }
            float4 v = *(const float4*)(W_ih + (size_t)(n0 + wn) * 768 + 512 + k1 + wq);
            ws[wq][wn]=v.x; ws[wq+1][wn]=v.y; ws[wq+2][wn]=v.z; ws[wq+3][wn]=v.w;
        }
        __syncthreads();
#pragma unroll 16
        for (int kk = 0; kk < 64; kk++) {
            float w = ws[kk][nl];
            unsigned long long w2 = pk2(w, w);
            fma2(acc0, *(const unsigned long long*)&hs[kk][bq*4],   w2);
            fma2(acc1, *(const unsigned long long*)&hs[kk][bq*4+2], w2);
        }
        __syncthreads();
    }
    int n = n0 + nl;
    const float* xr = g_xg + (size_t)t * 64 * GATES;
    float2 a = upk(acc0), b2 = upk(acc1);
    g_gates[(bq*4+0)*GATES+n] = xr[(bq*4+0)*GATES+n] + a.x;
    g_gates[(bq*4+1)*GATES+n] = xr[(bq*4+1)*GATES+n] + a.y;
    g_gates[(bq*4+2)*GATES+n] = xr[(bq*4+2)*GATES+n] + b2.x;
    g_gates[(bq*4+3)*GATES+n] = xr[(bq*4+3)*GATES+n] + b2.y;
}

// ---------------- per-step: LSTM pointwise ---------------------------------
__global__ void k_point(int t) {
    int idx = blockIdx.x * 256 + threadIdx.x;   // 0..32767
    int b = idx >> 9, d = idx & 511;
    const float* g = g_gates + b * GATES;
    float ig = g[d], fg = g[512 + d], gg = g[1024 + d], og = g[1536 + d];
    float c = g_c[idx];
    float cn = sigmoidf_(fg) * c + sigmoidf_(ig) * tanhf(gg);
    float hn = sigmoidf_(og) * tanhf(cn);
    g_c[idx] = cn;
    g_h[(t + 1) & 1][idx] = hn;
    g_Hall[((size_t)t * 64 + b) * 512 + d] = hn;
}

// ---------------- launch ----------------------------------------------------
extern "C" void kernel_launch(void* const* d_in, const int* in_sizes, int n_in,
                              void* d_out, int out_size) {
    const float* enc    = (const float*)d_in[0];
    const void*  caps   = d_in[1];
    const float* W_enc  = (const float*)d_in[2];
    const float* b_enc  = (const float*)d_in[3];
    const float* W_dec  = (const float*)d_in[4];
    const float* b_dec  = (const float*)d_in[5];
    const float* W_full = (const float*)d_in[6];
    // d_in[7] = b_full (softmax shift-invariant, unused)
    const float* emb    = (const float*)d_in[8];
    const float* W_ih   = (const float*)d_in[9];
    const float* b_ih   = (const float*)d_in[10];
    const float* W_hh   = (const float*)d_in[11];
    const float* b_hh   = (const float*)d_in[12];
    const float* W_fc   = (const float*)d_in[13];
    const float* b_fc   = (const float*)d_in[14];
    float* out = (float*)d_out;

    float *p_feats, *p_enc_att, *p_E, *p_xg, *p_bias2, *p_Hall;
    cudaGetSymbolAddress((void**)&p_feats,   g_feats);
    cudaGetSymbolAddress((void**)&p_enc_att, g_enc_att);
    cudaGetSymbolAddress((void**)&p_E,       g_E);
    cudaGetSymbolAddress((void**)&p_xg,      g_xg);
    cudaGetSymbolAddress((void**)&p_bias2,   g_bias2);
    cudaGetSymbolAddress((void**)&p_Hall,    g_Hall);

    k_init<<<264, 256>>>(b_ih, b_hh, caps);
    k_transpose<<<dim3(7, 8, 64), dim3(32, 8)>>>(enc);
    k_gather<<<T_STEPS * BATCH, 128>>>(caps, emb);
    // enc_att = feats @ W_enc + b_enc : [12544 x 512], K=256
    k_gemm2<false, false><<<dim3(4, 98), 256>>>(p_feats, ENC_C, W_enc, ATT_D, b_enc,
                                                p_enc_att, ATT_D,
                                                BATCH * PIX, ATT_D, ENC_C);
    // xg = E @ W_ih[:, :512]^T + (b_ih + b_hh) : [1280 x 2048], K=512
    k_gemm2<true, false><<<dim3(16, 10), 256>>>(p_E, EMB_D, W_ih, EMB_D + ENC_C, p_bias2,
                                                p_xg, GATES,
                                                T_STEPS * BATCH, GATES, EMB_D);
    for (int t = 0; t < T_STEPS; t++) {
        k_dec<<<32, 256>>>(W_dec, b_dec, t);
        k_att<<<BATCH, 256>>>(W_full, t);
        k_gates<<<128, 256>>>(W_hh, W_ih, t);
        k_point<<<128, 256>>>(t);
    }
    // out[b][t][:] = Hall @ W_fc + b_fc : [1280 x 30000], K=512 (row remap)
    k_gemm2<false, true><<<dim3(235, 10), 256>>>(p_Hall, DEC_D, W_fc, VOCAB, b_fc,
                                                 out, VOCAB,
                                                 T_STEPS * BATCH, VOCAB, DEC_D);
}

// round 6
// speedup vs baseline: 1.0832x; 1.0832x over previous
#include <cuda_runtime.h>
#include <cuda_bf16.h>
#include <math.h>
#include <stdint.h>

#define T_STEPS 20
#define BATCH   64
#define PIX     196
#define ENC_C   256
#define ATT_D   512
#define DEC_D   512
#define EMB_D   512
#define VOCAB   30000
#define VOCAB_P 30080
#define GATES   2048
#define FCK     1536        // split-bf16 K: [hi|hi|lo] x [hi|lo|hi]

// ---------------- device scratch (static; no allocations allowed) ----------
__device__ float g_feats[BATCH * PIX * ENC_C];      // [b][p][c]
__device__ float g_enc_att[BATCH * PIX * ATT_D];    // [b][p][a]
__device__ float g_E[T_STEPS * BATCH * EMB_D];      // row m = t*64+b
__device__ float g_xg[T_STEPS * BATCH * GATES];     // emb part of gates (+biases)
__device__ float g_dec[BATCH * ATT_D];              // h @ W_dec + b_dec
__device__ float g_gates[BATCH * GATES];
__device__ float g_h[2][BATCH * DEC_D];             // double-buffered hidden
__device__ float g_c[BATCH * DEC_D];
__device__ float g_ctx[BATCH * ENC_C];
__device__ float g_Hall[T_STEPS * BATCH * DEC_D];   // all h_t, row m = t*64+b
__device__ float g_bias2[GATES];                    // b_ih + b_hh
__device__ int   g_cap64;
// bf16 K-extended operands for the HMMA FC GEMM
__device__ __nv_bfloat16 g_Wext[(size_t)VOCAB_P * FCK];   // [n][k']
__device__ __nv_bfloat16 g_Hext[T_STEPS * BATCH * FCK];   // [m][k']

// ---------------- f32x2 helpers --------------------------------------------
__device__ __forceinline__ unsigned long long pk2(float lo, float hi) {
    unsigned long long r;
    asm("mov.b64 %0, {%1, %2};" : "=l"(r) : "f"(lo), "f"(hi));
    return r;
}
__device__ __forceinline__ void fma2(unsigned long long &d, unsigned long long a,
                                     unsigned long long b) {
    asm("fma.rn.f32x2 %0, %1, %2, %0;" : "+l"(d) : "l"(a), "l"(b));
}
__device__ __forceinline__ float2 upk(unsigned long long v) {
    float2 r;
    asm("mov.b64 {%0, %1}, %2;" : "=f"(r.x), "=f"(r.y) : "l"(v));
    return r;
}
__device__ __forceinline__ float sigmoidf_(float x) { return 1.f / (1.f + expf(-x)); }

__device__ __forceinline__ uint32_t smem_u32(const void* p) {
    uint32_t a;
    asm("{ .reg .u64 t; cvta.to.shared.u64 t, %1; cvt.u32.u64 %0, t; }" : "=r"(a) : "l"(p));
    return a;
}

// ---------------- init ------------------------------------------------------
__global__ void k_init(const float* __restrict__ b_ih, const float* __restrict__ b_hh,
                       const void* __restrict__ caps) {
    int idx = blockIdx.x * 256 + threadIdx.x;
    if (idx < BATCH * DEC_D) g_h[0][idx] = 0.f;
    else if (idx < 2 * BATCH * DEC_D) g_c[idx - BATCH * DEC_D] = 0.f;
    else if (idx < 2 * BATCH * DEC_D + GATES) {
        int n = idx - 2 * BATCH * DEC_D;
        g_bias2[n] = b_ih[n] + b_hh[n];
    }
    if (blockIdx.x == 0 && threadIdx.x == 0) {
        const int* ci = (const int*)caps;
        int all0 = 1;
        for (int i = 0; i < 64; i++) if (ci[2 * i + 1] != 0) { all0 = 0; break; }
        g_cap64 = all0;
    }
}

// ---------------- transpose [b][c][p] -> feats [b][p][c] -------------------
__global__ void k_transpose(const float* __restrict__ in) {
    __shared__ float tile[32][33];
    int b  = blockIdx.z;
    int p0 = blockIdx.x * 32;
    int c0 = blockIdx.y * 32;
    int tx = threadIdx.x, ty = threadIdx.y;
    const float* src = in + ((size_t)b * ENC_C + c0) * PIX + p0;
#pragma unroll
    for (int i = 0; i < 4; i++) {
        int c = ty + i * 8;
        if (p0 + tx < PIX) tile[c][tx] = src[c * PIX + tx];
    }
    __syncthreads();
    float* dst = g_feats + (size_t)b * PIX * ENC_C;
#pragma unroll
    for (int i = 0; i < 4; i++) {
        int p = ty + i * 8;
        if (p0 + p < PIX) dst[(size_t)(p0 + p) * ENC_C + c0 + tx] = tile[tx][p];
    }
}

// ---------------- embedding gather -----------------------------------------
__global__ void k_gather(const void* __restrict__ caps, const float* __restrict__ emb) {
    int m = blockIdx.x;
    int tt = m >> 6, b = m & 63;
    long long cap;
    if (g_cap64) cap = ((const long long*)caps)[b * T_STEPS + tt];
    else         cap = ((const int*)caps)[b * T_STEPS + tt];
    if ((unsigned long long)cap >= (unsigned long long)VOCAB) cap = 0;
    const float4* src = (const float4*)(emb + (size_t)cap * EMB_D);
    float4* dst = (float4*)(g_E + (size_t)m * EMB_D);
    dst[threadIdx.x] = src[threadIdx.x];
}

// ---------------- W_fc [512][30000] -> Wext [30080][1536] bf16 -------------
// Wext[n][k'] : k'<512 -> hi(W[k'][n]); k'<1024 -> lo(W[k'-512][n]); else hi.
__global__ void k_convWext(const float* __restrict__ W) {
    __shared__ float tile[32][33];
    int n0 = blockIdx.x * 32, k0 = blockIdx.y * 32;
    int tx = threadIdx.x, ty = threadIdx.y;
#pragma unroll
    for (int i = 0; i < 4; i++) {
        int k = ty + i * 8;
        int n = n0 + tx;
        tile[k][tx] = (n < VOCAB) ? W[(size_t)(k0 + k) * VOCAB + n] : 0.f;
    }
    __syncthreads();
#pragma unroll
    for (int i = 0; i < 4; i++) {
        int nr = ty + i * 8;
        float v = tile[tx][nr];            // = W[k0+tx][n0+nr]
        __nv_bfloat16 hi = __float2bfloat16(v);
        __nv_bfloat16 lo = __float2bfloat16(v - __bfloat162float(hi));
        size_t base = (size_t)(n0 + nr) * FCK + k0 + tx;
        g_Wext[base]        = hi;
        g_Wext[base + 512]  = lo;
        g_Wext[base + 1024] = hi;
    }
}

// ---------------- Hall -> Hext [1280][1536] bf16 ---------------------------
__global__ void k_convHext() {
    int idx = blockIdx.x * 256 + threadIdx.x;     // 1280*1536 = 1,966,080
    int m = idx / FCK, k = idx % FCK;
    int ks = (k >= 1024) ? k - 1024 : ((k >= 512) ? k - 512 : k);
    float v = g_Hall[m * 512 + ks];
    __nv_bfloat16 hi = __float2bfloat16(v);
    g_Hext[idx] = (k < 1024) ? hi : __float2bfloat16(v - __bfloat162float(hi));
}

// ---------------- single-buffered f32x2 GEMM (round-2 version) -------------
template <bool TRANSB>
__global__ __launch_bounds__(256, 2)
void k_gemm(const float* __restrict__ A, int lda,
            const float* __restrict__ B, int ldb,
            const float* __restrict__ bias,
            float* __restrict__ C, int ldc,
            int M, int N, int K) {
    __shared__ float As[16][132];
    __shared__ float Bs[16][68];
    const int t  = threadIdx.x;
    const int tx = t & 15, ty = t >> 4;
    const int m0 = blockIdx.y * 128, n0 = blockIdx.x * 64;

    unsigned long long acc[4][4];
#pragma unroll
    for (int i = 0; i < 4; i++)
#pragma unroll
        for (int j = 0; j < 4; j++) acc[i][j] = 0ull;

    for (int k0 = 0; k0 < K; k0 += 16) {
        {
            int i = t >> 1, kh = (t & 1) << 3;
            int m = m0 + i;
            float4 v0 = {0,0,0,0}, v1 = {0,0,0,0};
            if (m < M) {
                const float4* p = (const float4*)(A + (size_t)m * lda + k0 + kh);
                v0 = p[0]; v1 = p[1];
            }
            As[kh+0][i]=v0.x; As[kh+1][i]=v0.y; As[kh+2][i]=v0.z; As[kh+3][i]=v0.w;
            As[kh+4][i]=v1.x; As[kh+5][i]=v1.y; As[kh+6][i]=v1.z; As[kh+7][i]=v1.w;
        }
        if (!TRANSB) {
            int kk = t >> 4, nq = (t & 15) << 2;
            float4 v = {0,0,0,0};
            if (n0 + nq + 4 <= N)
                v = *(const float4*)(B + (size_t)(k0 + kk) * ldb + n0 + nq);
            Bs[kk][nq]=v.x; Bs[kk][nq+1]=v.y; Bs[kk][nq+2]=v.z; Bs[kk][nq+3]=v.w;
        } else {
            int n = t >> 2, kq = (t & 3) << 2;
            float4 v = {0,0,0,0};
            if (n0 + n < N)
                v = *(const float4*)(B + (size_t)(n0 + n) * ldb + k0 + kq);
            Bs[kq][n]=v.x; Bs[kq+1][n]=v.y; Bs[kq+2][n]=v.z; Bs[kq+3][n]=v.w;
        }
        __syncthreads();
#pragma unroll
        for (int kk = 0; kk < 16; kk++) {
            unsigned long long a2[4];
            a2[0] = *(const unsigned long long*)&As[kk][ty*8+0];
            a2[1] = *(const unsigned long long*)&As[kk][ty*8+2];
            a2[2] = *(const unsigned long long*)&As[kk][ty*8+4];
            a2[3] = *(const unsigned long long*)&As[kk][ty*8+6];
            float4 b4 = *(const float4*)&Bs[kk][tx*4];
            unsigned long long b2[4] = {pk2(b4.x,b4.x), pk2(b4.y,b4.y),
                                        pk2(b4.z,b4.z), pk2(b4.w,b4.w)};
#pragma unroll
            for (int i = 0; i < 4; i++)
#pragma unroll
                for (int j = 0; j < 4; j++) fma2(acc[i][j], a2[i], b2[j]);
        }
        __syncthreads();
    }
#pragma unroll
    for (int j = 0; j < 4; j++) {
        int col = n0 + tx * 4 + j;
        if (col >= N) continue;
        float bv = bias ? bias[col] : 0.f;
#pragma unroll
        for (int i = 0; i < 4; i++) {
            float2 v = upk(acc[i][j]);
            int m = m0 + ty * 8 + i * 2;
            if (m < M)     C[(size_t)m * ldc + col] = v.x + bv;
            if (m + 1 < M) C[(size_t)(m + 1) * ldc + col] = v.y + bv;
        }
    }
}

// ---------------- HMMA FC GEMM: out = Hext @ Wext^T + b_fc -----------------
// mma.sync m16n8k16 bf16 (baseline PTX, no 'a' feature needed).
// CTA tile 128x128, 8 warps (4m x 2n), warp tile 32x64, BK=32,
// cp.async double-buffered smem. Row stride 40 bf16 (20 banks): the 4B
// fragment loads are bank-conflict-free.
__global__ __launch_bounds__(256)
void k_fc_hmma(const float* __restrict__ b_fc, float* __restrict__ out) {
    __shared__ __nv_bfloat16 As[2][128][40];
    __shared__ __nv_bfloat16 Bs[2][128][40];
    const int tid = threadIdx.x, lane = tid & 31, wid = tid >> 5;
    const int wm = wid & 3, wn = wid >> 2;             // 4 x 2 warps
    const int m0 = blockIdx.x * 128;                   // 10 m-tiles (fast dim)
    const int n0 = blockIdx.y * 128;                   // 235 n-tiles

    float acc[2][8][4];
#pragma unroll
    for (int im = 0; im < 2; im++)
#pragma unroll
        for (int jn = 0; jn < 8; jn++)
#pragma unroll
            for (int q = 0; q < 4; q++) acc[im][jn][q] = 0.f;

    // loader: thread < 128 -> A row tid; else B row tid-128. 4 x 16B per chunk.
    const __nv_bfloat16* gsrc;
    uint32_t sdstA, sdstB;
    if (tid < 128) gsrc = g_Hext + (size_t)(m0 + tid) * FCK;
    else           gsrc = g_Wext + (size_t)(n0 + (tid - 128)) * FCK;
    sdstA = smem_u32(&As[0][tid & 127][0]);
    sdstB = smem_u32(&Bs[0][tid & 127][0]);
    const uint32_t sdst0 = (tid < 128) ? sdstA : sdstB;
    const uint32_t bufstep = (uint32_t)(128 * 40 * 2);   // bytes between buffers

    auto issue_chunk = [&](int c, int buf) {
        const __nv_bfloat16* src = gsrc + c * 32;
        uint32_t d = sdst0 + (uint32_t)buf * bufstep;
#pragma unroll
        for (int q = 0; q < 4; q++)
            asm volatile("cp.async.ca.shared.global [%0], [%1], 16;"
                         :: "r"(d + q * 16), "l"(src + q * 8));
        asm volatile("cp.async.commit_group;" ::: "memory");
    };

    issue_chunk(0, 0);

    const int nc = FCK / 32;   // 48
    for (int c = 0; c < nc; c++) {
        int buf = c & 1;
        if (c + 1 < nc) {
            issue_chunk(c + 1, buf ^ 1);
            asm volatile("cp.async.wait_group 1;" ::: "memory");
        } else {
            asm volatile("cp.async.wait_group 0;" ::: "memory");
        }
        __syncthreads();
#pragma unroll
        for (int ks = 0; ks < 2; ks++) {
            const int col = ks * 16 + (lane & 3) * 2;
            uint32_t a[2][4];
#pragma unroll
            for (int im = 0; im < 2; im++) {
                int r = wm * 32 + im * 16 + (lane >> 2);
                a[im][0] = *(const uint32_t*)&As[buf][r][col];
                a[im][1] = *(const uint32_t*)&As[buf][r + 8][col];
                a[im][2] = *(const uint32_t*)&As[buf][r][col + 8];
                a[im][3] = *(const uint32_t*)&As[buf][r + 8][col + 8];
            }
#pragma unroll
            for (int jn = 0; jn < 8; jn++) {
                int n = wn * 64 + jn * 8 + (lane >> 2);
                uint32_t b0 = *(const uint32_t*)&Bs[buf][n][col];
                uint32_t b1 = *(const uint32_t*)&Bs[buf][n][col + 8];
#pragma unroll
                for (int im = 0; im < 2; im++) {
                    asm volatile(
                        "mma.sync.aligned.m16n8k16.row.col.f32.bf16.bf16.f32 "
                        "{%0,%1,%2,%3}, {%4,%5,%6,%7}, {%8,%9}, {%0,%1,%2,%3};"
                        : "+f"(acc[im][jn][0]), "+f"(acc[im][jn][1]),
                          "+f"(acc[im][jn][2]), "+f"(acc[im][jn][3])
                        : "r"(a[im][0]), "r"(a[im][1]), "r"(a[im][2]), "r"(a[im][3]),
                          "r"(b0), "r"(b1));
                }
            }
        }
        __syncthreads();
    }

    // epilogue: c0,c1 -> row r; c2,c3 -> row r+8; cols (lane&3)*2, +1
#pragma unroll
    for (int im = 0; im < 2; im++) {
        int mbase = m0 + wm * 32 + im * 16 + (lane >> 2);
#pragma unroll
        for (int half = 0; half < 2; half++) {
            int m = mbase + half * 8;
            int orow = (m & 63) * T_STEPS + (m >> 6);     // out row = b*20 + t
            float* op = out + (size_t)orow * VOCAB;
#pragma unroll
            for (int jn = 0; jn < 8; jn++) {
                int col = n0 + wn * 64 + jn * 8 + (lane & 3) * 2;
                if (col < VOCAB) {
                    float2 v;
                    v.x = acc[im][jn][half * 2 + 0] + b_fc[col];
                    v.y = acc[im][jn][half * 2 + 1] + b_fc[col + 1];
                    *(float2*)(op + col) = v;
                }
            }
        }
    }
}

// ---------------- per-step: dec_att = h @ W_dec + b_dec --------------------
__global__ __launch_bounds__(256) void k_dec(const float* __restrict__ W_dec,
                                             const float* __restrict__ b_dec, int t) {
    __shared__ float hs[64][68];
    __shared__ float ws[64][17];
    int tid = threadIdx.x, n0 = blockIdx.x * 16;
    const float* hb = g_h[t & 1];
    int lb = tid & 63, kq = (tid >> 6) * 16;
    int wk = tid >> 2, wq = (tid & 3) * 4;
    int nl = tid & 15, bq = tid >> 4;
    unsigned long long acc0 = 0ull, acc1 = 0ull;
    for (int c = 0; c < 8; c++) {
        int k0 = c * 64;
#pragma unroll
        for (int j = 0; j < 4; j++) {
            float4 v = *(const float4*)(hb + lb * 512 + k0 + kq + j * 4);
            hs[kq+j*4+0][lb]=v.x; hs[kq+j*4+1][lb]=v.y;
            hs[kq+j*4+2][lb]=v.z; hs[kq+j*4+3][lb]=v.w;
        }
        {
            float4 v = *(const float4*)(W_dec + (size_t)(k0 + wk) * 512 + n0 + wq);
            ws[wk][wq]=v.x; ws[wk][wq+1]=v.y; ws[wk][wq+2]=v.z; ws[wk][wq+3]=v.w;
        }
        __syncthreads();
#pragma unroll 16
        for (int kk = 0; kk < 64; kk++) {
            float w = ws[kk][nl];
            unsigned long long w2 = pk2(w, w);
            fma2(acc0, *(const unsigned long long*)&hs[kk][bq*4],   w2);
            fma2(acc1, *(const unsigned long long*)&hs[kk][bq*4+2], w2);
        }
        __syncthreads();
    }
    int n = n0 + nl; float bv = b_dec[n];
    float2 a = upk(acc0), b2 = upk(acc1);
    g_dec[(bq*4+0)*512+n] = a.x + bv;
    g_dec[(bq*4+1)*512+n] = a.y + bv;
    g_dec[(bq*4+2)*512+n] = b2.x + bv;
    g_dec[(bq*4+3)*512+n] = b2.y + bv;
}

// ---------------- per-step: fused attention scores/softmax/context ---------
__global__ __launch_bounds__(256) void k_att(const float* __restrict__ W_full, int t) {
    __shared__ float dec_s[512], wf_s[512], sc_s[224];
    __shared__ float red[8];
    int b = blockIdx.x, tid = threadIdx.x;
    dec_s[tid] = g_dec[b*512+tid]; dec_s[tid+256] = g_dec[b*512+tid+256];
    wf_s[tid] = W_full[tid]; wf_s[tid+256] = W_full[tid+256];
    __syncthreads();
    int wp = tid >> 5, lane = tid & 31;
    for (int p = wp; p < PIX; p += 8) {
        const float* ea = g_enc_att + ((size_t)b * PIX + p) * ATT_D;
        float s = 0.f;
#pragma unroll 4
        for (int a = lane; a < 512; a += 32)
            s = fmaf(fmaxf(ea[a] + dec_s[a], 0.f), wf_s[a], s);
#pragma unroll
        for (int o = 16; o; o >>= 1) s += __shfl_xor_sync(0xffffffffu, s, o);
        if (!lane) sc_s[p] = s;      // +b_full omitted: softmax shift-invariant
    }
    __syncthreads();
    float v = (tid < PIX) ? sc_s[tid] : -1e30f;
    float mx = v;
#pragma unroll
    for (int o = 16; o; o >>= 1) mx = fmaxf(mx, __shfl_xor_sync(0xffffffffu, mx, o));
    if (!lane) red[wp] = mx;
    __syncthreads();
    if (tid == 0) { float m = red[0]; for (int i = 1; i < 8; i++) m = fmaxf(m, red[i]); red[0] = m; }
    __syncthreads();
    float e = (tid < PIX) ? expf(v - red[0]) : 0.f;
    float ss = e;
#pragma unroll
    for (int o = 16; o; o >>= 1) ss += __shfl_xor_sync(0xffffffffu, ss, o);
    __syncthreads();
    if (!lane) red[wp] = ss;
    __syncthreads();
    if (tid == 0) { float s = 0.f; for (int i = 0; i < 8; i++) s += red[i]; red[0] = s; }
    __syncthreads();
    if (tid < PIX) sc_s[tid] = e / red[0];
    __syncthreads();
    const float* fb = g_feats + (size_t)b * PIX * ENC_C;
    float cx = 0.f;
#pragma unroll 4
    for (int p = 0; p < PIX; p++) cx = fmaf(sc_s[p], fb[p * ENC_C + tid], cx);
    g_ctx[b * ENC_C + tid] = cx;
}

// ---------------- per-step: gates = xg + h@W_hh^T + ctx@W_ih[:,512:]^T -----
__global__ __launch_bounds__(256) void k_gates(const float* __restrict__ W_hh,
                                               const float* __restrict__ W_ih, int t) {
    __shared__ float hs[64][68];
    __shared__ float ws[64][17];
    int tid = threadIdx.x, n0 = blockIdx.x * 16;
    const float* hb = g_h[t & 1];
    int lb = tid & 63, kq = (tid >> 6) * 16;
    int wn = tid >> 4, wq = (tid & 15) * 4;
    int nl = tid & 15, bq = tid >> 4;
    unsigned long long acc0 = 0ull, acc1 = 0ull;
    for (int c = 0; c < 12; c++) {
        int k0 = c * 64;
        if (k0 < 512) {
#pragma unroll
            for (int j = 0; j < 4; j++) {
                float4 v = *(const float4*)(hb + lb * 512 + k0 + kq + j * 4);
                hs[kq+j*4+0][lb]=v.x; hs[kq+j*4+1][lb]=v.y;
                hs[kq+j*4+2][lb]=v.z; hs[kq+j*4+3][lb]=v.w;
            }
            float4 v = *(const float4*)(W_hh + (size_t)(n0 + wn) * 512 + k0 + wq);
            ws[wq][wn]=v.x; ws[wq+1][wn]=v.y; ws[wq+2][wn]=v.z; ws[wq+3][wn]=v.w;
        } else {
            int k1 = k0 - 512;
#pragma unroll
            for (int j = 0; j < 4; j++) {
                float4 v = *(const float4*)(g_ctx + lb * 256 + k1 + kq + j * 4);
                hs[kq+j*4+0][lb]=v.x; hs[kq+j*4+1][lb]=v.y;
                hs[kq+j*4+2][lb]=v.z; hs[kq+j*4+3][lb]=v.w;
            }
            float4 v = *(const float4*)(W_ih + (size_t)(n0 + wn) * 768 + 512 + k1 + wq);
            ws[wq][wn]=v.x; ws[wq+1][wn]=v.y; ws[wq+2][wn]=v.z; ws[wq+3][wn]=v.w;
        }
        __syncthreads();
#pragma unroll 16
        for (int kk = 0; kk < 64; kk++) {
            float w = ws[kk][nl];
            unsigned long long w2 = pk2(w, w);
            fma2(acc0, *(const unsigned long long*)&hs[kk][bq*4],   w2);
            fma2(acc1, *(const unsigned long long*)&hs[kk][bq*4+2], w2);
        }
        __syncthreads();
    }
    int n = n0 + nl;
    const float* xr = g_xg + (size_t)t * 64 * GATES;
    float2 a = upk(acc0), b2 = upk(acc1);
    g_gates[(bq*4+0)*GATES+n] = xr[(bq*4+0)*GATES+n] + a.x;
    g_gates[(bq*4+1)*GATES+n] = xr[(bq*4+1)*GATES+n] + a.y;
    g_gates[(bq*4+2)*GATES+n] = xr[(bq*4+2)*GATES+n] + b2.x;
    g_gates[(bq*4+3)*GATES+n] = xr[(bq*4+3)*GATES+n] + b2.y;
}

// ---------------- per-step: LSTM pointwise ---------------------------------
__global__ void k_point(int t) {
    int idx = blockIdx.x * 256 + threadIdx.x;   // 0..32767
    int b = idx >> 9, d = idx & 511;
    const float* g = g_gates + b * GATES;
    float ig = g[d], fg = g[512 + d], gg = g[1024 + d], og = g[1536 + d];
    float c = g_c[idx];
    float cn = sigmoidf_(fg) * c + sigmoidf_(ig) * tanhf(gg);
    float hn = sigmoidf_(og) * tanhf(cn);
    g_c[idx] = cn;
    g_h[(t + 1) & 1][idx] = hn;
    g_Hall[((size_t)t * 64 + b) * 512 + d] = hn;
}

// ---------------- launch ----------------------------------------------------
extern "C" void kernel_launch(void* const* d_in, const int* in_sizes, int n_in,
                              void* d_out, int out_size) {
    const float* enc    = (const float*)d_in[0];
    const void*  caps   = d_in[1];
    const float* W_enc  = (const float*)d_in[2];
    const float* b_enc  = (const float*)d_in[3];
    const float* W_dec  = (const float*)d_in[4];
    const float* b_dec  = (const float*)d_in[5];
    const float* W_full = (const float*)d_in[6];
    // d_in[7] = b_full (softmax shift-invariant, unused)
    const float* emb    = (const float*)d_in[8];
    const float* W_ih   = (const float*)d_in[9];
    const float* b_ih   = (const float*)d_in[10];
    const float* W_hh   = (const float*)d_in[11];
    const float* b_hh   = (const float*)d_in[12];
    const float* W_fc   = (const float*)d_in[13];
    const float* b_fc   = (const float*)d_in[14];
    float* out = (float*)d_out;

    float *p_feats, *p_enc_att, *p_E, *p_xg, *p_bias2;
    cudaGetSymbolAddress((void**)&p_feats,   g_feats);
    cudaGetSymbolAddress((void**)&p_enc_att, g_enc_att);
    cudaGetSymbolAddress((void**)&p_E,       g_E);
    cudaGetSymbolAddress((void**)&p_xg,      g_xg);
    cudaGetSymbolAddress((void**)&p_bias2,   g_bias2);

    k_init<<<264, 256>>>(b_ih, b_hh, caps);
    k_transpose<<<dim3(7, 8, 64), dim3(32, 8)>>>(enc);
    k_gather<<<T_STEPS * BATCH, 128>>>(caps, emb);
    k_convWext<<<dim3(VOCAB_P / 32, 16), dim3(32, 8)>>>(W_fc);
    // enc_att = feats @ W_enc + b_enc : [12544 x 512], K=256
    k_gemm<false><<<dim3(8, 98), 256>>>(p_feats, ENC_C, W_enc, ATT_D, b_enc,
                                        p_enc_att, ATT_D, BATCH * PIX, ATT_D, ENC_C);
    // xg = E @ W_ih[:, :512]^T + (b_ih + b_hh) : [1280 x 2048], K=512
    k_gemm<true><<<dim3(32, 10), 256>>>(p_E, EMB_D, W_ih, EMB_D + ENC_C, p_bias2,
                                        p_xg, GATES, T_STEPS * BATCH, GATES, EMB_D);
    for (int t = 0; t < T_STEPS; t++) {
        k_dec<<<32, 256>>>(W_dec, b_dec, t);
        k_att<<<BATCH, 256>>>(W_full, t);
        k_gates<<<128, 256>>>(W_hh, W_ih, t);
        k_point<<<128, 256>>>(t);
    }
    k_convHext<<<7680, 256>>>();
    // FC: tensor-core bf16 HMMA GEMM, K=1536 (split), grid.x = m (B reuse in L2)
    k_fc_hmma<<<dim3(10, 235), 256>>>(b_fc, out);
}

// round 7
// speedup vs baseline: 1.1567x; 1.0678x over previous
#include <cuda_runtime.h>
#include <cuda_bf16.h>
#include <math.h>
#include <stdint.h>

#define T_STEPS 20
#define BATCH   64
#define PIX     196
#define ENC_C   256
#define ATT_D   512
#define DEC_D   512
#define EMB_D   512
#define VOCAB   30000
#define VOCAB_P 30080
#define GATES   2048
#define FCK     1536        // split-bf16 K: [hi|hi|lo] x [hi|lo|hi]

// ---------------- device scratch (static; no allocations allowed) ----------
__device__ float g_feats[BATCH * PIX * ENC_C];      // [b][p][c]
__device__ float g_enc_att[BATCH * PIX * ATT_D];    // [b][p][a]
__device__ float g_E[T_STEPS * BATCH * EMB_D];      // row m = t*64+b
__device__ float g_xg[T_STEPS * BATCH * GATES];     // emb part of gates (+biases)
__device__ float g_h[2][BATCH * DEC_D];             // double-buffered hidden
__device__ float g_c[BATCH * DEC_D];
__device__ float g_ctx[BATCH * ENC_C];
__device__ float g_Hall[T_STEPS * BATCH * DEC_D];   // all h_t, row m = t*64+b
__device__ float g_bias2[GATES];                    // b_ih + b_hh
__device__ int   g_cap64;
// bf16 K-extended operands for the HMMA FC GEMM
__device__ __nv_bfloat16 g_Wext[(size_t)VOCAB_P * FCK];   // [n][k']
__device__ __nv_bfloat16 g_Hext[T_STEPS * BATCH * FCK];   // [m][k']

// ---------------- helpers ---------------------------------------------------
__device__ __forceinline__ unsigned long long pk2(float lo, float hi) {
    unsigned long long r;
    asm("mov.b64 %0, {%1, %2};" : "=l"(r) : "f"(lo), "f"(hi));
    return r;
}
__device__ __forceinline__ void fma2(unsigned long long &d, unsigned long long a,
                                     unsigned long long b) {
    asm("fma.rn.f32x2 %0, %1, %2, %0;" : "+l"(d) : "l"(a), "l"(b));
}
__device__ __forceinline__ float2 upk(unsigned long long v) {
    float2 r;
    asm("mov.b64 {%0, %1}, %2;" : "=f"(r.x), "=f"(r.y) : "l"(v));
    return r;
}
__device__ __forceinline__ float sigmoidf_(float x) { return 1.f / (1.f + expf(-x)); }

__device__ __forceinline__ uint32_t smem_u32(const void* p) {
    uint32_t a;
    asm("{ .reg .u64 t; cvta.to.shared.u64 t, %1; cvt.u32.u64 %0, t; }" : "=r"(a) : "l"(p));
    return a;
}

// ---------------- init ------------------------------------------------------
__global__ void k_init(const float* __restrict__ b_ih, const float* __restrict__ b_hh,
                       const void* __restrict__ caps) {
    int idx = blockIdx.x * 256 + threadIdx.x;
    if (idx < BATCH * DEC_D) g_h[0][idx] = 0.f;
    else if (idx < 2 * BATCH * DEC_D) g_c[idx - BATCH * DEC_D] = 0.f;
    else if (idx < 2 * BATCH * DEC_D + GATES) {
        int n = idx - 2 * BATCH * DEC_D;
        g_bias2[n] = b_ih[n] + b_hh[n];
    }
    if (blockIdx.x == 0 && threadIdx.x == 0) {
        const int* ci = (const int*)caps;
        int all0 = 1;
        for (int i = 0; i < 64; i++) if (ci[2 * i + 1] != 0) { all0 = 0; break; }
        g_cap64 = all0;
    }
}

// ---------------- transpose [b][c][p] -> feats [b][p][c] -------------------
__global__ void k_transpose(const float* __restrict__ in) {
    __shared__ float tile[32][33];
    int b  = blockIdx.z;
    int p0 = blockIdx.x * 32;
    int c0 = blockIdx.y * 32;
    int tx = threadIdx.x, ty = threadIdx.y;
    const float* src = in + ((size_t)b * ENC_C + c0) * PIX + p0;
#pragma unroll
    for (int i = 0; i < 4; i++) {
        int c = ty + i * 8;
        if (p0 + tx < PIX) tile[c][tx] = src[c * PIX + tx];
    }
    __syncthreads();
    float* dst = g_feats + (size_t)b * PIX * ENC_C;
#pragma unroll
    for (int i = 0; i < 4; i++) {
        int p = ty + i * 8;
        if (p0 + p < PIX) dst[(size_t)(p0 + p) * ENC_C + c0 + tx] = tile[tx][p];
    }
}

// ---------------- embedding gather -----------------------------------------
__global__ void k_gather(const void* __restrict__ caps, const float* __restrict__ emb) {
    int m = blockIdx.x;
    int tt = m >> 6, b = m & 63;
    long long cap;
    if (g_cap64) cap = ((const long long*)caps)[b * T_STEPS + tt];
    else         cap = ((const int*)caps)[b * T_STEPS + tt];
    if ((unsigned long long)cap >= (unsigned long long)VOCAB) cap = 0;
    const float4* src = (const float4*)(emb + (size_t)cap * EMB_D);
    float4* dst = (float4*)(g_E + (size_t)m * EMB_D);
    dst[threadIdx.x] = src[threadIdx.x];
}

// ---------------- W_fc [512][30000] -> Wext [30080][1536] bf16 -------------
__global__ void k_convWext(const float* __restrict__ W) {
    __shared__ float tile[32][33];
    int n0 = blockIdx.x * 32, k0 = blockIdx.y * 32;
    int tx = threadIdx.x, ty = threadIdx.y;
#pragma unroll
    for (int i = 0; i < 4; i++) {
        int k = ty + i * 8;
        int n = n0 + tx;
        tile[k][tx] = (n < VOCAB) ? W[(size_t)(k0 + k) * VOCAB + n] : 0.f;
    }
    __syncthreads();
#pragma unroll
    for (int i = 0; i < 4; i++) {
        int nr = ty + i * 8;
        float v = tile[tx][nr];            // = W[k0+tx][n0+nr]
        __nv_bfloat16 hi = __float2bfloat16(v);
        __nv_bfloat16 lo = __float2bfloat16(v - __bfloat162float(hi));
        size_t base = (size_t)(n0 + nr) * FCK + k0 + tx;
        g_Wext[base]        = hi;
        g_Wext[base + 512]  = lo;
        g_Wext[base + 1024] = hi;
    }
}

// ---------------- Hall -> Hext [1280][1536] bf16 ---------------------------
__global__ void k_convHext() {
    int idx = blockIdx.x * 256 + threadIdx.x;     // 1280*1536 = 1,966,080
    int m = idx / FCK, k = idx % FCK;
    int ks = (k >= 1024) ? k - 1024 : ((k >= 512) ? k - 512 : k);
    float v = g_Hall[m * 512 + ks];
    __nv_bfloat16 hi = __float2bfloat16(v);
    g_Hext[idx] = (k < 1024) ? hi : __float2bfloat16(v - __bfloat162float(hi));
}

// ---------------- single-buffered f32x2 GEMM (round-2 version) -------------
template <bool TRANSB>
__global__ __launch_bounds__(256, 2)
void k_gemm(const float* __restrict__ A, int lda,
            const float* __restrict__ B, int ldb,
            const float* __restrict__ bias,
            float* __restrict__ C, int ldc,
            int M, int N, int K) {
    __shared__ float As[16][132];
    __shared__ float Bs[16][68];
    const int t  = threadIdx.x;
    const int tx = t & 15, ty = t >> 4;
    const int m0 = blockIdx.y * 128, n0 = blockIdx.x * 64;

    unsigned long long acc[4][4];
#pragma unroll
    for (int i = 0; i < 4; i++)
#pragma unroll
        for (int j = 0; j < 4; j++) acc[i][j] = 0ull;

    for (int k0 = 0; k0 < K; k0 += 16) {
        {
            int i = t >> 1, kh = (t & 1) << 3;
            int m = m0 + i;
            float4 v0 = {0,0,0,0}, v1 = {0,0,0,0};
            if (m < M) {
                const float4* p = (const float4*)(A + (size_t)m * lda + k0 + kh);
                v0 = p[0]; v1 = p[1];
            }
            As[kh+0][i]=v0.x; As[kh+1][i]=v0.y; As[kh+2][i]=v0.z; As[kh+3][i]=v0.w;
            As[kh+4][i]=v1.x; As[kh+5][i]=v1.y; As[kh+6][i]=v1.z; As[kh+7][i]=v1.w;
        }
        if (!TRANSB) {
            int kk = t >> 4, nq = (t & 15) << 2;
            float4 v = {0,0,0,0};
            if (n0 + nq + 4 <= N)
                v = *(const float4*)(B + (size_t)(k0 + kk) * ldb + n0 + nq);
            Bs[kk][nq]=v.x; Bs[kk][nq+1]=v.y; Bs[kk][nq+2]=v.z; Bs[kk][nq+3]=v.w;
        } else {
            int n = t >> 2, kq = (t & 3) << 2;
            float4 v = {0,0,0,0};
            if (n0 + n < N)
                v = *(const float4*)(B + (size_t)(n0 + n) * ldb + k0 + kq);
            Bs[kq][n]=v.x; Bs[kq+1][n]=v.y; Bs[kq+2][n]=v.z; Bs[kq+3][n]=v.w;
        }
        __syncthreads();
#pragma unroll
        for (int kk = 0; kk < 16; kk++) {
            unsigned long long a2[4];
            a2[0] = *(const unsigned long long*)&As[kk][ty*8+0];
            a2[1] = *(const unsigned long long*)&As[kk][ty*8+2];
            a2[2] = *(const unsigned long long*)&As[kk][ty*8+4];
            a2[3] = *(const unsigned long long*)&As[kk][ty*8+6];
            float4 b4 = *(const float4*)&Bs[kk][tx*4];
            unsigned long long b2[4] = {pk2(b4.x,b4.x), pk2(b4.y,b4.y),
                                        pk2(b4.z,b4.z), pk2(b4.w,b4.w)};
#pragma unroll
            for (int i = 0; i < 4; i++)
#pragma unroll
                for (int j = 0; j < 4; j++) fma2(acc[i][j], a2[i], b2[j]);
        }
        __syncthreads();
    }
#pragma unroll
    for (int j = 0; j < 4; j++) {
        int col = n0 + tx * 4 + j;
        if (col >= N) continue;
        float bv = bias ? bias[col] : 0.f;
#pragma unroll
        for (int i = 0; i < 4; i++) {
            float2 v = upk(acc[i][j]);
            int m = m0 + ty * 8 + i * 2;
            if (m < M)     C[(size_t)m * ldc + col] = v.x + bv;
            if (m + 1 < M) C[(size_t)(m + 1) * ldc + col] = v.y + bv;
        }
    }
}

// ---------------- HMMA FC GEMM with ldmatrix fragment loads ----------------
__global__ __launch_bounds__(256)
void k_fc_hmma(const float* __restrict__ b_fc, float* __restrict__ out) {
    __shared__ __nv_bfloat16 As[2][128][40];
    __shared__ __nv_bfloat16 Bs[2][128][40];
    const int tid = threadIdx.x, lane = tid & 31, wid = tid >> 5;
    const int wm = wid & 3, wn = wid >> 2;             // 4 x 2 warps
    const int m0 = blockIdx.x * 128;                   // 10 m-tiles (fast dim)
    const int n0 = blockIdx.y * 128;                   // 235 n-tiles

    float acc[2][8][4];
#pragma unroll
    for (int im = 0; im < 2; im++)
#pragma unroll
        for (int jn = 0; jn < 8; jn++)
#pragma unroll
            for (int q = 0; q < 4; q++) acc[im][jn][q] = 0.f;

    // ldmatrix per-lane byte offsets (pitch = 40 bf16 = 80 B)
    const uint32_t as_base = smem_u32(&As[0][0][0]);
    const uint32_t bs_base = smem_u32(&Bs[0][0][0]);
    const uint32_t aoff0 = (uint32_t)(wm * 32 + (lane & 15)) * 80u + ((lane >> 4) << 4);
    const uint32_t boff0 = (uint32_t)(wn * 64 + (lane & 15)) * 80u + ((lane >> 4) << 4);

    // loader: thread < 128 -> A row tid; else B row tid-128. 4 x 16B per chunk.
    const __nv_bfloat16* gsrc;
    if (tid < 128) gsrc = g_Hext + (size_t)(m0 + tid) * FCK;
    else           gsrc = g_Wext + (size_t)(n0 + (tid - 128)) * FCK;
    const uint32_t sdstA = smem_u32(&As[0][tid & 127][0]);
    const uint32_t sdstB = smem_u32(&Bs[0][tid & 127][0]);
    const uint32_t sdst0 = (tid < 128) ? sdstA : sdstB;
    const uint32_t bufstep = 10240u;                   // 128*40*2 bytes

    auto issue_chunk = [&](int c, int buf) {
        const __nv_bfloat16* src = gsrc + c * 32;
        uint32_t d = sdst0 + (uint32_t)buf * bufstep;
#pragma unroll
        for (int q = 0; q < 4; q++)
            asm volatile("cp.async.ca.shared.global [%0], [%1], 16;"
                         :: "r"(d + q * 16), "l"(src + q * 8));
        asm volatile("cp.async.commit_group;" ::: "memory");
    };

    issue_chunk(0, 0);

    const int nc = FCK / 32;   // 48
    for (int c = 0; c < nc; c++) {
        int buf = c & 1;
        if (c + 1 < nc) {
            issue_chunk(c + 1, buf ^ 1);
            asm volatile("cp.async.wait_group 1;" ::: "memory");
        } else {
            asm volatile("cp.async.wait_group 0;" ::: "memory");
        }
        __syncthreads();
        const uint32_t bb = (uint32_t)buf * bufstep;
#pragma unroll
        for (int ks = 0; ks < 2; ks++) {
            uint32_t a[2][4];
#pragma unroll
            for (int im = 0; im < 2; im++) {
                uint32_t ad = as_base + bb + aoff0 + (uint32_t)im * 1280u + (uint32_t)ks * 32u;
                asm volatile("ldmatrix.sync.aligned.m8n8.x4.shared.b16 {%0,%1,%2,%3}, [%4];"
                             : "=r"(a[im][0]), "=r"(a[im][1]), "=r"(a[im][2]), "=r"(a[im][3])
                             : "r"(ad));
            }
            uint32_t bfr[8][2];
#pragma unroll
            for (int q = 0; q < 4; q++) {
                uint32_t r0, r1, r2, r3;
                uint32_t bd = bs_base + bb + boff0 + (uint32_t)q * 1280u + (uint32_t)ks * 32u;
                asm volatile("ldmatrix.sync.aligned.m8n8.x4.shared.b16 {%0,%1,%2,%3}, [%4];"
                             : "=r"(r0), "=r"(r1), "=r"(r2), "=r"(r3) : "r"(bd));
                bfr[2*q][0] = r0; bfr[2*q+1][0] = r1;
                bfr[2*q][1] = r2; bfr[2*q+1][1] = r3;
            }
#pragma unroll
            for (int jn = 0; jn < 8; jn++) {
#pragma unroll
                for (int im = 0; im < 2; im++) {
                    asm volatile(
                        "mma.sync.aligned.m16n8k16.row.col.f32.bf16.bf16.f32 "
                        "{%0,%1,%2,%3}, {%4,%5,%6,%7}, {%8,%9}, {%0,%1,%2,%3};"
                        : "+f"(acc[im][jn][0]), "+f"(acc[im][jn][1]),
                          "+f"(acc[im][jn][2]), "+f"(acc[im][jn][3])
                        : "r"(a[im][0]), "r"(a[im][1]), "r"(a[im][2]), "r"(a[im][3]),
                          "r"(bfr[jn][0]), "r"(bfr[jn][1]));
                }
            }
        }
        __syncthreads();
    }

    // epilogue: c0,c1 -> row r; c2,c3 -> row r+8; cols (lane&3)*2, +1
#pragma unroll
    for (int im = 0; im < 2; im++) {
        int mbase = m0 + wm * 32 + im * 16 + (lane >> 2);
#pragma unroll
        for (int half = 0; half < 2; half++) {
            int m = mbase + half * 8;
            int orow = (m & 63) * T_STEPS + (m >> 6);     // out row = b*20 + t
            float* op = out + (size_t)orow * VOCAB;
#pragma unroll
            for (int jn = 0; jn < 8; jn++) {
                int col = n0 + wn * 64 + jn * 8 + (lane & 3) * 2;
                if (col < VOCAB) {
                    float2 v;
                    v.x = acc[im][jn][half * 2 + 0] + b_fc[col];
                    v.y = acc[im][jn][half * 2 + 1] + b_fc[col + 1];
                    *(float2*)(op + col) = v;
                }
            }
        }
    }
}

// ---------------- per-step fused attention (dec GEMM + scores + ctx) -------
// one block per batch element.
__global__ __launch_bounds__(256) void k_att2(const float* __restrict__ W_dec,
                                              const float* __restrict__ b_dec,
                                              const float* __restrict__ W_full, int t) {
    __shared__ __align__(16) float h_s[512];
    __shared__ __align__(16) float dec_s[512];
    __shared__ __align__(16) float wf_s[512];
    __shared__ float sc_s[224];
    __shared__ float red[8];
    int b = blockIdx.x, tid = threadIdx.x;
    const float* hb = g_h[t & 1] + b * 512;
    h_s[tid] = hb[tid]; h_s[tid + 256] = hb[tid + 256];
    wf_s[tid] = W_full[tid]; wf_s[tid + 256] = W_full[tid + 256];
    __syncthreads();
    {   // dec = h @ W_dec + b_dec ; thread owns cols 2*tid, 2*tid+1 (float2)
        float2 bv = *(const float2*)(b_dec + 2 * tid);
        float a0 = bv.x, a1 = bv.y;
        const float* wp_ = W_dec + 2 * tid;
#pragma unroll 8
        for (int k = 0; k < 512; k++) {
            float hk = h_s[k];
            float2 w = *(const float2*)(wp_ + (size_t)k * 512);
            a0 = fmaf(hk, w.x, a0);
            a1 = fmaf(hk, w.y, a1);
        }
        dec_s[2 * tid] = a0; dec_s[2 * tid + 1] = a1;
    }
    __syncthreads();
    int wp = tid >> 5, lane = tid & 31;
    const float4* dec4 = (const float4*)dec_s;
    const float4* wf4  = (const float4*)wf_s;
    for (int p = wp; p < PIX; p += 8) {
        const float4* ea = (const float4*)(g_enc_att + ((size_t)b * PIX + p) * ATT_D);
        float s = 0.f;
#pragma unroll 2
        for (int a4 = lane; a4 < 128; a4 += 32) {
            float4 e = ea[a4], dd = dec4[a4], wf = wf4[a4];
            s = fmaf(fmaxf(e.x + dd.x, 0.f), wf.x, s);
            s = fmaf(fmaxf(e.y + dd.y, 0.f), wf.y, s);
            s = fmaf(fmaxf(e.z + dd.z, 0.f), wf.z, s);
            s = fmaf(fmaxf(e.w + dd.w, 0.f), wf.w, s);
        }
#pragma unroll
        for (int o = 16; o; o >>= 1) s += __shfl_xor_sync(0xffffffffu, s, o);
        if (!lane) sc_s[p] = s;      // +b_full omitted: softmax shift-invariant
    }
    __syncthreads();
    float v = (tid < PIX) ? sc_s[tid] : -1e30f;
    float mx = v;
#pragma unroll
    for (int o = 16; o; o >>= 1) mx = fmaxf(mx, __shfl_xor_sync(0xffffffffu, mx, o));
    if (!lane) red[wp] = mx;
    __syncthreads();
    if (tid == 0) { float m = red[0]; for (int i = 1; i < 8; i++) m = fmaxf(m, red[i]); red[0] = m; }
    __syncthreads();
    float e = (tid < PIX) ? expf(v - red[0]) : 0.f;
    float ss = e;
#pragma unroll
    for (int o = 16; o; o >>= 1) ss += __shfl_xor_sync(0xffffffffu, ss, o);
    __syncthreads();
    if (!lane) red[wp] = ss;
    __syncthreads();
    if (tid == 0) { float s = 0.f; for (int i = 0; i < 8; i++) s += red[i]; red[0] = s; }
    __syncthreads();
    if (tid < PIX) sc_s[tid] = e / red[0];
    __syncthreads();
    const float* fb = g_feats + (size_t)b * PIX * ENC_C;
    float cx = 0.f;
#pragma unroll 4
    for (int p = 0; p < PIX; p++) cx = fmaf(sc_s[p], fb[p * ENC_C + tid], cx);
    g_ctx[b * ENC_C + tid] = cx;
}

// ---------------- per-step fused gates GEMM + LSTM pointwise ---------------
// 128 blocks; block g owns the (i,f,g,o) quadruple for d-cols g*4..g*4+3
// (16 gate columns), K = 768 (h 512 + ctx 256). Pointwise fused in-block.
__global__ __launch_bounds__(256) void k_gp(const float* __restrict__ W_hh,
                                            const float* __restrict__ W_ih, int t) {
    __shared__ float hs[64][68];
    __shared__ float ws[64][17];
    __shared__ float gs[64][17];
    int tid = threadIdx.x;
    int d0 = blockIdx.x * 4;
    const float* hb = g_h[t & 1];
    int lb = tid & 63, kq = (tid >> 6) * 16;       // hs loader
    int wn = tid >> 4, wq = (tid & 15) * 4;        // ws loader: col wn, k wq..wq+3
    int nl = tid & 15, bq = tid >> 4;              // compute
    const int growL = (wn >> 2) * 512 + d0 + (wn & 3);
    unsigned long long acc0 = 0ull, acc1 = 0ull;
    for (int c = 0; c < 12; c++) {
        int k0 = c * 64;
        if (k0 < 512) {
#pragma unroll
            for (int j = 0; j < 4; j++) {
                float4 v = *(const float4*)(hb + lb * 512 + k0 + kq + j * 4);
                hs[kq+j*4+0][lb]=v.x; hs[kq+j*4+1][lb]=v.y;
                hs[kq+j*4+2][lb]=v.z; hs[kq+j*4+3][lb]=v.w;
            }
            float4 v = *(const float4*)(W_hh + (size_t)growL * 512 + k0 + wq);
            ws[wq][wn]=v.x; ws[wq+1][wn]=v.y; ws[wq+2][wn]=v.z; ws[wq+3][wn]=v.w;
        } else {
            int k1 = k0 - 512;
#pragma unroll
            for (int j = 0; j < 4; j++) {
                float4 v = *(const float4*)(g_ctx + lb * 256 + k1 + kq + j * 4);
                hs[kq+j*4+0][lb]=v.x; hs[kq+j*4+1][lb]=v.y;
                hs[kq+j*4+2][lb]=v.z; hs[kq+j*4+3][lb]=v.w;
            }
            float4 v = *(const float4*)(W_ih + (size_t)growL * 768 + 512 + k1 + wq);
            ws[wq][wn]=v.x; ws[wq+1][wn]=v.y; ws[wq+2][wn]=v.z; ws[wq+3][wn]=v.w;
        }
        __syncthreads();
#pragma unroll 16
        for (int kk = 0; kk < 64; kk++) {
            float w = ws[kk][nl];
            unsigned long long w2 = pk2(w, w);
            fma2(acc0, *(const unsigned long long*)&hs[kk][bq*4],   w2);
            fma2(acc1, *(const unsigned long long*)&hs[kk][bq*4+2], w2);
        }
        __syncthreads();
    }
    {
        const int grow = (nl >> 2) * 512 + d0 + (nl & 3);
        const float* xr = g_xg + (size_t)t * 64 * GATES + grow;
        float2 a = upk(acc0), b2 = upk(acc1);
        gs[bq*4+0][nl] = xr[(bq*4+0)*GATES] + a.x;
        gs[bq*4+1][nl] = xr[(bq*4+1)*GATES] + a.y;
        gs[bq*4+2][nl] = xr[(bq*4+2)*GATES] + b2.x;
        gs[bq*4+3][nl] = xr[(bq*4+3)*GATES] + b2.y;
    }
    __syncthreads();
    {   // pointwise: thread -> (b = tid>>2, dl = tid&3)
        int b = tid >> 2, dl = tid & 3;
        float ig = gs[b][dl],      fg = gs[b][4 + dl];
        float gg = gs[b][8 + dl],  og = gs[b][12 + dl];
        int d = d0 + dl, idx = b * 512 + d;
        float c0 = g_c[idx];
        float cn = sigmoidf_(fg) * c0 + sigmoidf_(ig) * tanhf(gg);
        float hn = sigmoidf_(og) * tanhf(cn);
        g_c[idx] = cn;
        g_h[(t + 1) & 1][idx] = hn;
        g_Hall[((size_t)t * 64 + b) * 512 + d] = hn;
    }
}

// ---------------- launch ----------------------------------------------------
extern "C" void kernel_launch(void* const* d_in, const int* in_sizes, int n_in,
                              void* d_out, int out_size) {
    const float* enc    = (const float*)d_in[0];
    const void*  caps   = d_in[1];
    const float* W_enc  = (const float*)d_in[2];
    const float* b_enc  = (const float*)d_in[3];
    const float* W_dec  = (const float*)d_in[4];
    const float* b_dec  = (const float*)d_in[5];
    const float* W_full = (const float*)d_in[6];
    // d_in[7] = b_full (softmax shift-invariant, unused)
    const float* emb    = (const float*)d_in[8];
    const float* W_ih   = (const float*)d_in[9];
    const float* b_ih   = (const float*)d_in[10];
    const float* W_hh   = (const float*)d_in[11];
    const float* b_hh   = (const float*)d_in[12];
    const float* W_fc   = (const float*)d_in[13];
    const float* b_fc   = (const float*)d_in[14];
    float* out = (float*)d_out;

    float *p_feats, *p_enc_att, *p_E, *p_xg, *p_bias2;
    cudaGetSymbolAddress((void**)&p_feats,   g_feats);
    cudaGetSymbolAddress((void**)&p_enc_att, g_enc_att);
    cudaGetSymbolAddress((void**)&p_E,       g_E);
    cudaGetSymbolAddress((void**)&p_xg,      g_xg);
    cudaGetSymbolAddress((void**)&p_bias2,   g_bias2);

    k_init<<<264, 256>>>(b_ih, b_hh, caps);
    k_transpose<<<dim3(7, 8, 64), dim3(32, 8)>>>(enc);
    k_gather<<<T_STEPS * BATCH, 128>>>(caps, emb);
    k_convWext<<<dim3(VOCAB_P / 32, 16), dim3(32, 8)>>>(W_fc);
    // enc_att = feats @ W_enc + b_enc : [12544 x 512], K=256
    k_gemm<false><<<dim3(8, 98), 256>>>(p_feats, ENC_C, W_enc, ATT_D, b_enc,
                                        p_enc_att, ATT_D, BATCH * PIX, ATT_D, ENC_C);
    // xg = E @ W_ih[:, :512]^T + (b_ih + b_hh) : [1280 x 2048], K=512
    k_gemm<true><<<dim3(32, 10), 256>>>(p_E, EMB_D, W_ih, EMB_D + ENC_C, p_bias2,
                                        p_xg, GATES, T_STEPS * BATCH, GATES, EMB_D);
    for (int t = 0; t < T_STEPS; t++) {
        k_att2<<<BATCH, 256>>>(W_dec, b_dec, W_full, t);
        k_gp<<<128, 256>>>(W_hh, W_ih, t);
    }
    k_convHext<<<7680, 256>>>();
    // FC: tensor-core bf16 HMMA GEMM (ldmatrix), K=1536 split
    k_fc_hmma<<<dim3(10, 235), 256>>>(b_fc, out);
}